// round 14
// baseline (speedup 1.0000x reference)
#include <cuda_runtime.h>
#include <math.h>

#define BB 128
#define QQ 500
#define NCLS 80
#define TT 64
#define NT 1024
#define CSTR 513   // column-major stride: bank = (col + q) % 32 -> conflict-free
#define FULL 0xffffffffu
#define SMEM_SZ (TT * CSTR * 4)   // 131,328 B dynamic (Cm only)
#define DEADK 0xFFFFFFFFu
#define CHUNK 125                 // q-chunk for the ccost table
#define FSTR 129                  // F stride: (s*129+ql)%32 distinct per s

__device__ __forceinline__ unsigned f2ord(float f) {
    unsigned u = __float_as_uint(f);
    return (u & 0x80000000u) ? ~u : (u | 0x80000000u);
}

// warp-cooperative exact (value, ravel) min over one smem column (R9-proven)
__device__ __forceinline__ void colscan(const float* __restrict__ Cm, int col,
                                        int lane, unsigned& mv, unsigned& mr) {
    const float* p = Cm + col * CSTR;
    unsigned best = 0xFFFFFFFFu, bq = 0;
    #pragma unroll
    for (int it = 0; it < 16; it++) {
        int q = lane + (it << 5);
        if (q < QQ) {
            unsigned u = f2ord(p[q]);
            if (u < best) { best = u; bq = (unsigned)q; }
        }
    }
    mv = __reduce_min_sync(FULL, best);
    unsigned cr = (best == mv) ? ((bq << 6) | (unsigned)col) : 0xFFFFFFFFu;
    mr = __reduce_min_sync(FULL, cr);
}

__global__ __launch_bounds__(NT, 1)
void hungarian_fused(const float* __restrict__ logits,   // [B,Q,C]
                     const float* __restrict__ pboxes,   // [B,Q,4]
                     const int*   __restrict__ tids,     // [B,T]
                     const float* __restrict__ tboxes,   // [B,T,4]
                     const float* __restrict__ imgsz,    // [B,4]
                     float*       __restrict__ out)
{
    extern __shared__ float Cm[];           // [64][513]
    __shared__ float4  s_tr[TT];
    __shared__ float4  s_tn[TT];
    __shared__ float   s_ta[TT];
    __shared__ int     s_cls[TT];
    __shared__ float4  s_pr[QQ];            // raw pred boxes
    __shared__ float4  s_bn[QQ];            // normalized pred boxes
    __shared__ float   s_pa[QQ];            // pred areas
    __shared__ float   F[TT * FSTR];        // ccost table for one q-chunk
    __shared__ int     s_first[TT];         // first t' with same class
    __shared__ int     s_slotof[TT];        // t -> compact slot
    __shared__ int     s_slotcls[TT];       // slot -> class id
    __shared__ unsigned s_val[TT], s_rav[TT];

    const int b = blockIdx.x, tid = threadIdx.x;
    const int lane = tid & 31, wrp = tid >> 5;

    const float inv0 = 1.0f / imgsz[b * 4 + 0];
    const float inv1 = 1.0f / imgsz[b * 4 + 1];
    const float inv2 = 1.0f / imgsz[b * 4 + 2];
    const float inv3 = 1.0f / imgsz[b * 4 + 3];

    if (tid < TT) {
        float4 tb = ((const float4*)tboxes)[b * TT + tid];
        s_tr[tid] = tb;
        s_tn[tid] = make_float4(tb.x * inv0, tb.y * inv1, tb.z * inv2, tb.w * inv3);
        s_ta[tid] = (tb.z - tb.x) * (tb.w - tb.y);
        s_cls[tid] = tids[b * TT + tid];
    }
    if (tid < QQ) {
        float4 pb = ((const float4*)pboxes)[b * QQ + tid];
        s_pr[tid] = pb;
        s_bn[tid] = make_float4(pb.x * inv0, pb.y * inv1, pb.z * inv2, pb.w * inv3);
        s_pa[tid] = (pb.z - pb.x) * (pb.w - pb.y);
    }
    __syncthreads();

    // ---- class dedup: slot_of[t], slotcls[slot], U ----
    if (tid < TT) {
        int c = s_cls[tid];
        int first = tid;
        for (int t2 = 0; t2 < TT; t2++)
            if (s_cls[t2] == c) { first = t2; break; }
        s_first[tid] = first;
    }
    __syncthreads();
    if (tid < TT) {
        int fr = s_first[tid];
        int slot = 0;
        for (int t2 = 0; t2 < fr; t2++) slot += (s_first[t2] == t2);
        s_slotof[tid] = slot;
        if (fr == tid) s_slotcls[slot] = s_cls[tid];
    }
    const int U = __syncthreads_count(tid < TT && s_first[tid] == tid);

    // ---- Phase 1: per-chunk ccost table + box assembly ----
    const int t  = tid & 63;
    const int qg = tid >> 6;                 // 0..15
    const float4 tr = s_tr[t];
    const float4 tn = s_tn[t];
    const float  ta = s_ta[t];
    const int    slot = s_slotof[t];

    const float* lg   = logits + (size_t)b * QQ * NCLS;
    float*       Cout = out    + (size_t)b * QQ * TT;

    #pragma unroll 1
    for (int ch = 0; ch < 4; ch++) {
        const int q0 = ch * CHUNK;
        const int total = U * CHUNK;

        // 1b: packed distinct-(class,q) focal-cost evaluations (bit-identical ops)
        #pragma unroll 1
        for (int idx = tid; idx < total; idx += NT) {
            int s  = idx / CHUNK;
            int ql = idx - s * CHUNK;
            float x = __ldg(lg + (q0 + ql) * NCLS + s_slotcls[s]);
            float p = 1.0f / (1.0f + expf(-x));
            float omp = 1.0f - p;
            float pos = 0.25f * omp * omp * (-logf(p + 1e-8f));
            float neg = 0.75f * p * p * (-log1pf(-p + 1e-8f));
            F[s * FSTR + ql] = pos - neg;
        }
        __syncthreads();

        // 1c: box part + assembly, 2 independent chains (R13 pattern)
        #pragma unroll
        for (int k2 = 0; k2 < 4; k2++) {
            int qla = qg + (k2 << 5);            // <= 15+96=111 < 125: always valid
            int qlb = qla + 16;                  // <= 127: guard < 125
            {
                int q = q0 + qla;
                float4 pb = s_pr[q], bn = s_bn[q];
                float pa = s_pa[q];
                float ccost = F[slot * FSTR + qla];
                float l1 = fabsf(bn.x - tn.x) + fabsf(bn.y - tn.y)
                         + fabsf(bn.z - tn.z) + fabsf(bn.w - tn.w);
                float iwd = fmaxf(fminf(pb.z, tr.z) - fmaxf(pb.x, tr.x), 0.0f);
                float ihd = fmaxf(fminf(pb.w, tr.w) - fmaxf(pb.y, tr.y), 0.0f);
                float inter = iwd * ihd;
                float uni = pa + ta - inter;
                float iou = inter / uni;
                float ewd = fmaxf(fmaxf(pb.z, tr.z) - fminf(pb.x, tr.x), 0.0f);
                float ehd = fmaxf(fmaxf(pb.w, tr.w) - fminf(pb.y, tr.y), 0.0f);
                float enc = ewd * ehd;
                float giou = iou - (enc - uni) / enc;
                float cost = 5.0f * l1 + 2.0f * ccost - 2.0f * giou;
                Cm[t * CSTR + q] = cost;
                Cout[q * TT + t] = cost;
            }
            if (qlb < CHUNK) {
                int q = q0 + qlb;
                float4 pb = s_pr[q], bn = s_bn[q];
                float pa = s_pa[q];
                float ccost = F[slot * FSTR + qlb];
                float l1 = fabsf(bn.x - tn.x) + fabsf(bn.y - tn.y)
                         + fabsf(bn.z - tn.z) + fabsf(bn.w - tn.w);
                float iwd = fmaxf(fminf(pb.z, tr.z) - fmaxf(pb.x, tr.x), 0.0f);
                float ihd = fmaxf(fminf(pb.w, tr.w) - fmaxf(pb.y, tr.y), 0.0f);
                float inter = iwd * ihd;
                float uni = pa + ta - inter;
                float iou = inter / uni;
                float ewd = fmaxf(fmaxf(pb.z, tr.z) - fminf(pb.x, tr.x), 0.0f);
                float ehd = fmaxf(fmaxf(pb.w, tr.w) - fminf(pb.y, tr.y), 0.0f);
                float enc = ewd * ehd;
                float giou = iou - (enc - uni) / enc;
                float cost = 5.0f * l1 + 2.0f * ccost - 2.0f * giou;
                Cm[t * CSTR + q] = cost;
                Cout[q * TT + t] = cost;
            }
        }
        __syncthreads();   // F reused next chunk
    }

    // ---- Phase 2: initial per-column (value, ravel) keys (R9) ----
    {
        unsigned mv, mr;
        colscan(Cm, wrp, lane, mv, mr);
        if (lane == 0) { s_val[wrp] = mv; s_rav[wrp] = mr; }
        colscan(Cm, wrp + 32, lane, mv, mr);
        if (lane == 0) { s_val[wrp + 32] = mv; s_rav[wrp + 32] = mr; }
    }
    __syncthreads();

    if (wrp != 0) return;   // greedy: warp 0 only

    // ---- Phase 3: greedy (R9-proven verbatim) ----
    unsigned v0 = s_val[lane],      r0 = s_rav[lane];        // col = lane
    unsigned v1 = s_val[lane + 32], r1 = s_rav[lane + 32];   // col = lane+32
    const float FINF = __int_as_float(0x7F800000);

    float* rows_out = out + (size_t)BB * QQ * TT + (size_t)b * TT;
    float* cols_out = rows_out + (size_t)BB * TT;

    #pragma unroll 1
    for (int s = 0; s < TT; s++) {
        unsigned m = __reduce_min_sync(FULL, v0 < v1 ? v0 : v1);
        unsigned cand = 0xFFFFFFFFu;
        if (v0 == m) cand = r0;
        if (v1 == m && r1 < cand) cand = r1;
        unsigned r = __reduce_min_sync(FULL, cand);   // exact (value, ravel) tie-break

        int i = (int)(r >> 6);
        int j = (int)(r & 63u);
        if (lane == 0) { rows_out[s] = (float)i; cols_out[s] = (float)j; }
        if (s == TT - 1) break;

        // kill column j
        if (lane == (j & 31)) { if (j < 32) v0 = DEADK; else v1 = DEADK; }

        // rescan needs from register state before poisoning
        bool n0 = (v0 != DEADK) && ((r0 >> 6) == (unsigned)i);
        bool n1 = (v1 != DEADK) && ((r1 >> 6) == (unsigned)i);

        // poison row i in every column -> future scans maskless
        Cm[lane * CSTR + i] = FINF;
        Cm[(lane + 32) * CSTR + i] = FINF;

        unsigned bal0 = __ballot_sync(FULL, n0);
        unsigned bal1 = __ballot_sync(FULL, n1);
        if (bal0 | bal1) {
            __syncwarp();   // poisons visible before rescans
            while (bal0) {
                int c = __ffs(bal0) - 1; bal0 &= bal0 - 1;
                unsigned mv, mr;
                colscan(Cm, c, lane, mv, mr);
                if (lane == c) { v0 = mv; r0 = mr; }
            }
            while (bal1) {
                int c = __ffs(bal1) - 1; bal1 &= bal1 - 1;
                unsigned mv, mr;
                colscan(Cm, c + 32, lane, mv, mr);
                if (lane == c) { v1 = mv; r1 = mr; }
            }
        }
    }
}

extern "C" void kernel_launch(void* const* d_in, const int* in_sizes, int n_in,
                              void* d_out, int out_size) {
    const float* logits = (const float*)d_in[0];   // [128,500,80]
    const float* pboxes = (const float*)d_in[1];   // [128,500,4]
    const int*   tids   = (const int*)  d_in[2];   // [128,64]
    const float* tboxes = (const float*)d_in[3];   // [128,64,4]
    const float* imgsz  = (const float*)d_in[4];   // [128,4]
    float* out = (float*)d_out;

    cudaFuncSetAttribute(hungarian_fused,
                         cudaFuncAttributeMaxDynamicSharedMemorySize, SMEM_SZ);
    hungarian_fused<<<BB, NT, SMEM_SZ>>>(logits, pboxes, tids, tboxes, imgsz, out);
}

// round 15
// speedup vs baseline: 1.0262x; 1.0262x over previous
#include <cuda_runtime.h>
#include <math.h>

#define BB 128
#define QQ 500
#define NCLS 80
#define TT 64
#define FULL 0xffffffffu

__device__ __forceinline__ unsigned f2ord(float f) {
    unsigned u = __float_as_uint(f);
    return (u & 0x80000000u) ? ~u : (u | 0x80000000u);
}

// ================= Kernel A: cost matrix (R5-proven verbatim) =================
#define KA_THREADS 256

__global__ __launch_bounds__(KA_THREADS)
void cost_kernel(const float* __restrict__ logits,   // [B,Q,C]
                 const float* __restrict__ pboxes,   // [B,Q,4]
                 const int*   __restrict__ tids,     // [B,T]
                 const float* __restrict__ tboxes,   // [B,T,4]
                 const float* __restrict__ imgsz,    // [B,4]
                 float*       __restrict__ out)      // [B,Q,T]
{
    __shared__ float4 s_tr[TT];
    __shared__ float4 s_tn[TT];
    __shared__ float  s_ta[TT];
    __shared__ int    s_cls[TT];

    const int b   = blockIdx.y;
    const int tid = threadIdx.x;

    const float inv0 = 1.0f / imgsz[b * 4 + 0];
    const float inv1 = 1.0f / imgsz[b * 4 + 1];
    const float inv2 = 1.0f / imgsz[b * 4 + 2];
    const float inv3 = 1.0f / imgsz[b * 4 + 3];

    if (tid < TT) {
        float4 tb = ((const float4*)tboxes)[b * TT + tid];
        s_tr[tid] = tb;
        s_tn[tid] = make_float4(tb.x * inv0, tb.y * inv1, tb.z * inv2, tb.w * inv3);
        s_ta[tid] = (tb.z - tb.x) * (tb.w - tb.y);
        s_cls[tid] = tids[b * TT + tid];
    }
    __syncthreads();

    const int t = tid & 63;
    const float4 tr = s_tr[t];
    const float4 tn = s_tn[t];
    const float  ta = s_ta[t];
    const int    cl = s_cls[t];

    const float* lg   = logits + (size_t)b * QQ * NCLS;
    float*       Cout = out    + (size_t)b * QQ * TT;

    #pragma unroll
    for (int rep = 0; rep < 8; rep++) {
        int q = blockIdx.x * 32 + rep * 4 + (tid >> 6);
        if (q >= QQ) break;

        float4 pb = ((const float4*)pboxes)[b * QQ + q];
        float bnx = pb.x * inv0, bny = pb.y * inv1;
        float bnz = pb.z * inv2, bnw = pb.w * inv3;
        float pa  = (pb.z - pb.x) * (pb.w - pb.y);

        float x = __ldg(lg + q * NCLS + cl);
        float p = 1.0f / (1.0f + expf(-x));
        float omp = 1.0f - p;
        float pos = 0.25f * omp * omp * (-logf(p + 1e-8f));
        float neg = 0.75f * p * p * (-log1pf(-p + 1e-8f));
        float ccost = pos - neg;

        float l1 = fabsf(bnx - tn.x) + fabsf(bny - tn.y)
                 + fabsf(bnz - tn.z) + fabsf(bnw - tn.w);

        float iwd = fmaxf(fminf(pb.z, tr.z) - fmaxf(pb.x, tr.x), 0.0f);
        float ihd = fmaxf(fminf(pb.w, tr.w) - fmaxf(pb.y, tr.y), 0.0f);
        float inter = iwd * ihd;
        float uni = pa + ta - inter;
        float iou = inter / uni;
        float ewd = fmaxf(fmaxf(pb.z, tr.z) - fminf(pb.x, tr.x), 0.0f);
        float ehd = fmaxf(fmaxf(pb.w, tr.w) - fminf(pb.y, tr.y), 0.0f);
        float enc = ewd * ehd;
        float giou = iou - (enc - uni) / enc;

        Cout[q * TT + t] = 5.0f * l1 + 2.0f * ccost - 2.0f * giou;
    }
}

// ================= Kernel B: assignment (fast load + R9 greedy) =================
#define KB_THREADS 1024
#define CSTR 513   // column-major stride: bank = (col + q) % 32 -> conflict-free
#define KB_SMEM (TT * CSTR * 4)
#define DEADK 0xFFFFFFFFu

// warp-cooperative exact (value, ravel) min over one smem column (R9-proven)
__device__ __forceinline__ void colscan(const float* __restrict__ Cm, int col,
                                        int lane, unsigned& mv, unsigned& mr) {
    const float* p = Cm + col * CSTR;
    unsigned best = 0xFFFFFFFFu, bq = 0;
    #pragma unroll
    for (int it = 0; it < 16; it++) {
        int q = lane + (it << 5);
        if (q < QQ) {
            unsigned u = f2ord(p[q]);
            if (u < best) { best = u; bq = (unsigned)q; }
        }
    }
    mv = __reduce_min_sync(FULL, best);
    unsigned cr = (best == mv) ? ((bq << 6) | (unsigned)col) : 0xFFFFFFFFu;
    mr = __reduce_min_sync(FULL, cr);
}

__global__ __launch_bounds__(KB_THREADS, 1)
void assign_kernel(const float* __restrict__ C,    // [B,Q,T]
                   float*       __restrict__ out)
{
    extern __shared__ float Cm[];           // [64][513]
    __shared__ unsigned s_val[TT], s_rav[TT];

    const int b = blockIdx.x, tid = threadIdx.x;
    const int lane = tid & 31, wrp = tid >> 5;
    const float* Cg = C + (size_t)b * QQ * TT;

    // ---- load + transpose: 8 independent LDG.128 per thread (MLP 8) ----
    {
        float4 v[8];
        #pragma unroll
        for (int k = 0; k < 8; k++)
            v[k] = ((const float4*)Cg)[tid + k * KB_THREADS];   // all issued up-front
        #pragma unroll
        for (int k = 0; k < 8; k++) {
            int i = tid + k * KB_THREADS;   // < 8192
            int q = i >> 4;
            int j = (i & 15) << 2;
            Cm[(j + 0) * CSTR + q] = v[k].x;
            Cm[(j + 1) * CSTR + q] = v[k].y;
            Cm[(j + 2) * CSTR + q] = v[k].z;
            Cm[(j + 3) * CSTR + q] = v[k].w;
        }
    }
    __syncthreads();

    // ---- init: 2 colscans per warp (32 warps cover 64 columns) ----
    {
        unsigned mv, mr;
        colscan(Cm, wrp, lane, mv, mr);
        if (lane == 0) { s_val[wrp] = mv; s_rav[wrp] = mr; }
        colscan(Cm, wrp + 32, lane, mv, mr);
        if (lane == 0) { s_val[wrp + 32] = mv; s_rav[wrp + 32] = mr; }
    }
    __syncthreads();

    if (wrp != 0) return;   // greedy: warp 0 only

    // ---- greedy (R9-proven verbatim) ----
    unsigned v0 = s_val[lane],      r0 = s_rav[lane];        // col = lane
    unsigned v1 = s_val[lane + 32], r1 = s_rav[lane + 32];   // col = lane+32
    const float FINF = __int_as_float(0x7F800000);

    float* rows_out = out + (size_t)BB * QQ * TT + (size_t)b * TT;
    float* cols_out = rows_out + (size_t)BB * TT;

    #pragma unroll 1
    for (int s = 0; s < TT; s++) {
        unsigned m = __reduce_min_sync(FULL, v0 < v1 ? v0 : v1);
        unsigned cand = 0xFFFFFFFFu;
        if (v0 == m) cand = r0;
        if (v1 == m && r1 < cand) cand = r1;
        unsigned r = __reduce_min_sync(FULL, cand);   // exact (value, ravel) tie-break

        int i = (int)(r >> 6);
        int j = (int)(r & 63u);
        if (lane == 0) { rows_out[s] = (float)i; cols_out[s] = (float)j; }
        if (s == TT - 1) break;

        // kill column j
        if (lane == (j & 31)) { if (j < 32) v0 = DEADK; else v1 = DEADK; }

        // rescan needs from register state before poisoning
        bool n0 = (v0 != DEADK) && ((r0 >> 6) == (unsigned)i);
        bool n1 = (v1 != DEADK) && ((r1 >> 6) == (unsigned)i);

        // poison row i in every column -> future scans maskless
        Cm[lane * CSTR + i] = FINF;
        Cm[(lane + 32) * CSTR + i] = FINF;

        unsigned bal0 = __ballot_sync(FULL, n0);
        unsigned bal1 = __ballot_sync(FULL, n1);
        if (bal0 | bal1) {
            __syncwarp();   // poisons visible before rescans
            while (bal0) {
                int c = __ffs(bal0) - 1; bal0 &= bal0 - 1;
                unsigned mv, mr;
                colscan(Cm, c, lane, mv, mr);
                if (lane == c) { v0 = mv; r0 = mr; }
            }
            while (bal1) {
                int c = __ffs(bal1) - 1; bal1 &= bal1 - 1;
                unsigned mv, mr;
                colscan(Cm, c + 32, lane, mv, mr);
                if (lane == c) { v1 = mv; r1 = mr; }
            }
        }
    }
}

extern "C" void kernel_launch(void* const* d_in, const int* in_sizes, int n_in,
                              void* d_out, int out_size) {
    const float* logits = (const float*)d_in[0];   // [128,500,80]
    const float* pboxes = (const float*)d_in[1];   // [128,500,4]
    const int*   tids   = (const int*)  d_in[2];   // [128,64]
    const float* tboxes = (const float*)d_in[3];   // [128,64,4]
    const float* imgsz  = (const float*)d_in[4];   // [128,4]
    float* out = (float*)d_out;

    dim3 gA((QQ + 31) / 32, BB);
    cost_kernel<<<gA, KA_THREADS>>>(logits, pboxes, tids, tboxes, imgsz, out);

    cudaFuncSetAttribute(assign_kernel,
                         cudaFuncAttributeMaxDynamicSharedMemorySize, KB_SMEM);
    assign_kernel<<<BB, KB_THREADS, KB_SMEM>>>(out, out);
}

// round 16
// speedup vs baseline: 1.1128x; 1.0845x over previous
#include <cuda_runtime.h>
#include <math.h>

#define BB 128
#define QQ 500
#define NCLS 80
#define TT 64
#define NT 1024
#define CSTR 513   // column-major stride: bank = (col + q) % 32 -> conflict-free
#define FULL 0xffffffffu
#define SMEM_SZ (TT * CSTR * 4)   // 131,328 B dynamic (Km only)
#define DEADK 0xFFFFFFFFu

__device__ __forceinline__ unsigned f2ord(float f) {
    unsigned u = __float_as_uint(f);
    return (u & 0x80000000u) ? ~u : (u | 0x80000000u);
}

// warp-cooperative exact (key, ravel) min over one key column.
// Keys are f2ord(cost): order-preserving bijection => identical semantics to floats.
__device__ __forceinline__ void colscan(const unsigned* __restrict__ Km, int col,
                                        int lane, unsigned& mv, unsigned& mr) {
    const unsigned* p = Km + col * CSTR;
    unsigned best = 0xFFFFFFFFu, bq = 0;
    #pragma unroll
    for (int it = 0; it < 16; it++) {
        int q = lane + (it << 5);
        if (q < QQ) {
            unsigned u = p[q];
            if (u < best) { best = u; bq = (unsigned)q; }   // ascending q: min row on tie
        }
    }
    mv = __reduce_min_sync(FULL, best);
    unsigned cr = (best == mv) ? ((bq << 6) | (unsigned)col) : 0xFFFFFFFFu;
    mr = __reduce_min_sync(FULL, cr);
}

// one cost element; bit-identical ops to all passing rounds
__device__ __forceinline__ float cost_elem(float4 pb, float4 bn, float pa, float x,
                                           float4 tr, float4 tn, float ta) {
    float p = 1.0f / (1.0f + expf(-x));
    float omp = 1.0f - p;
    float pos = 0.25f * omp * omp * (-logf(p + 1e-8f));
    float neg = 0.75f * p * p * (-log1pf(-p + 1e-8f));
    float ccost = pos - neg;

    float l1 = fabsf(bn.x - tn.x) + fabsf(bn.y - tn.y)
             + fabsf(bn.z - tn.z) + fabsf(bn.w - tn.w);

    float iwd = fmaxf(fminf(pb.z, tr.z) - fmaxf(pb.x, tr.x), 0.0f);
    float ihd = fmaxf(fminf(pb.w, tr.w) - fmaxf(pb.y, tr.y), 0.0f);
    float inter = iwd * ihd;
    float uni = pa + ta - inter;
    float iou = inter / uni;
    float ewd = fmaxf(fmaxf(pb.z, tr.z) - fminf(pb.x, tr.x), 0.0f);
    float ehd = fmaxf(fmaxf(pb.w, tr.w) - fminf(pb.y, tr.y), 0.0f);
    float enc = ewd * ehd;
    float giou = iou - (enc - uni) / enc;

    return 5.0f * l1 + 2.0f * ccost - 2.0f * giou;
}

__global__ __launch_bounds__(NT, 1)
void hungarian_fused(const float* __restrict__ logits,   // [B,Q,C]
                     const float* __restrict__ pboxes,   // [B,Q,4]
                     const int*   __restrict__ tids,     // [B,T]
                     const float* __restrict__ tboxes,   // [B,T,4]
                     const float* __restrict__ imgsz,    // [B,4]
                     float*       __restrict__ out)
{
    extern __shared__ unsigned Km[];        // [64][513] f2ord keys
    __shared__ float4  s_tr[TT];
    __shared__ float4  s_tn[TT];
    __shared__ float   s_ta[TT];
    __shared__ int     s_cls[TT];
    __shared__ float4  s_pr[QQ];            // raw pred boxes
    __shared__ float4  s_bn[QQ];            // normalized pred boxes
    __shared__ float   s_pa[QQ];            // pred areas
    __shared__ unsigned s_val[TT], s_rav[TT];

    const int b = blockIdx.x, tid = threadIdx.x;
    const int lane = tid & 31, wrp = tid >> 5;

    const float inv0 = 1.0f / imgsz[b * 4 + 0];
    const float inv1 = 1.0f / imgsz[b * 4 + 1];
    const float inv2 = 1.0f / imgsz[b * 4 + 2];
    const float inv3 = 1.0f / imgsz[b * 4 + 3];

    if (tid < TT) {
        float4 tb = ((const float4*)tboxes)[b * TT + tid];
        s_tr[tid] = tb;
        s_tn[tid] = make_float4(tb.x * inv0, tb.y * inv1, tb.z * inv2, tb.w * inv3);
        s_ta[tid] = (tb.z - tb.x) * (tb.w - tb.y);
        s_cls[tid] = tids[b * TT + tid];
    }
    if (tid < QQ) {
        float4 pb = ((const float4*)pboxes)[b * QQ + tid];
        s_pr[tid] = pb;
        s_bn[tid] = make_float4(pb.x * inv0, pb.y * inv1, pb.z * inv2, pb.w * inv3);
        s_pa[tid] = (pb.z - pb.x) * (pb.w - pb.y);
    }
    __syncthreads();

    // ---- Phase 1: 2 independent q-chains + software-pipelined logits prefetch ----
    const int t  = tid & 63;
    const int qg = tid >> 6;                 // 0..15
    const float4 tr = s_tr[t];
    const float4 tn = s_tn[t];
    const float  ta = s_ta[t];
    const int    cl = s_cls[t];

    const float* lg   = logits + (size_t)b * QQ * NCLS;
    float*       Cout = out    + (size_t)b * QQ * TT;

    float xA = __ldg(lg + qg * NCLS + cl);
    float xB = __ldg(lg + (qg + 16) * NCLS + cl);

    #pragma unroll 1
    for (int k2 = 0; k2 < 15; k2++) {
        int qa = qg + (k2 << 5);             // <= 495: always valid
        int qb = qa + 16;                    // <= 479 in-loop: always valid

        // prefetch next iteration's logits (hides LDG latency behind this body)
        int qa_n = qa + 32;                  // <= 495: always valid
        int qb_n = qb + 32;                  // == 496+qg at k2=14: guard
        float xA_n = __ldg(lg + qa_n * NCLS + cl);
        float xB_n = (qb_n < QQ) ? __ldg(lg + qb_n * NCLS + cl) : 0.0f;

        float cA = cost_elem(s_pr[qa], s_bn[qa], s_pa[qa], xA, tr, tn, ta);
        float cB = cost_elem(s_pr[qb], s_bn[qb], s_pa[qb], xB, tr, tn, ta);
        Km[t * CSTR + qa] = f2ord(cA);
        Cout[qa * TT + t] = cA;
        Km[t * CSTR + qb] = f2ord(cB);
        Cout[qb * TT + t] = cB;

        xA = xA_n; xB = xB_n;
    }
    {   // tail: qa = qg+480 always valid; qb = qg+496 valid only for qg < 4
        int qa = qg + 480;
        float cA = cost_elem(s_pr[qa], s_bn[qa], s_pa[qa], xA, tr, tn, ta);
        Km[t * CSTR + qa] = f2ord(cA);
        Cout[qa * TT + t] = cA;
        if (qg < 4) {
            int qb = qa + 16;
            float cB = cost_elem(s_pr[qb], s_bn[qb], s_pa[qb], xB, tr, tn, ta);
            Km[t * CSTR + qb] = f2ord(cB);
            Cout[qb * TT + t] = cB;
        }
    }
    __syncthreads();

    // ---- Phase 2: initial per-column (key, ravel) minima ----
    {
        unsigned mv, mr;
        colscan(Km, wrp, lane, mv, mr);
        if (lane == 0) { s_val[wrp] = mv; s_rav[wrp] = mr; }
        colscan(Km, wrp + 32, lane, mv, mr);
        if (lane == 0) { s_val[wrp + 32] = mv; s_rav[wrp + 32] = mr; }
    }
    __syncthreads();

    if (wrp != 0) return;   // greedy: warp 0 only

    // ---- Phase 3: greedy (R9-proven step body, key-array form) ----
    unsigned v0 = s_val[lane],      r0 = s_rav[lane];        // col = lane
    unsigned v1 = s_val[lane + 32], r1 = s_rav[lane + 32];   // col = lane+32

    float* rows_out = out + (size_t)BB * QQ * TT + (size_t)b * TT;
    float* cols_out = rows_out + (size_t)BB * TT;

    #pragma unroll 1
    for (int s = 0; s < TT; s++) {
        unsigned m = __reduce_min_sync(FULL, v0 < v1 ? v0 : v1);
        unsigned cand = 0xFFFFFFFFu;
        if (v0 == m) cand = r0;
        if (v1 == m && r1 < cand) cand = r1;
        unsigned r = __reduce_min_sync(FULL, cand);   // exact (value, ravel) tie-break

        int i = (int)(r >> 6);
        int j = (int)(r & 63u);
        if (lane == 0) { rows_out[s] = (float)i; cols_out[s] = (float)j; }
        if (s == TT - 1) break;

        // kill column j
        if (lane == (j & 31)) { if (j < 32) v0 = DEADK; else v1 = DEADK; }

        // rescan needs from register state before poisoning
        bool n0 = (v0 != DEADK) && ((r0 >> 6) == (unsigned)i);
        bool n1 = (v1 != DEADK) && ((r1 >> 6) == (unsigned)i);

        // poison row i in every column (max key) -> future scans maskless
        Km[lane * CSTR + i] = 0xFFFFFFFFu;
        Km[(lane + 32) * CSTR + i] = 0xFFFFFFFFu;

        unsigned bal0 = __ballot_sync(FULL, n0);
        unsigned bal1 = __ballot_sync(FULL, n1);
        if (bal0 | bal1) {
            __syncwarp();   // poisons visible before rescans
            while (bal0) {
                int c = __ffs(bal0) - 1; bal0 &= bal0 - 1;
                unsigned mv, mr;
                colscan(Km, c, lane, mv, mr);
                if (lane == c) { v0 = mv; r0 = mr; }
            }
            while (bal1) {
                int c = __ffs(bal1) - 1; bal1 &= bal1 - 1;
                unsigned mv, mr;
                colscan(Km, c + 32, lane, mv, mr);
                if (lane == c) { v1 = mv; r1 = mr; }
            }
        }
    }
}

extern "C" void kernel_launch(void* const* d_in, const int* in_sizes, int n_in,
                              void* d_out, int out_size) {
    const float* logits = (const float*)d_in[0];   // [128,500,80]
    const float* pboxes = (const float*)d_in[1];   // [128,500,4]
    const int*   tids   = (const int*)  d_in[2];   // [128,64]
    const float* tboxes = (const float*)d_in[3];   // [128,64,4]
    const float* imgsz  = (const float*)d_in[4];   // [128,4]
    float* out = (float*)d_out;

    cudaFuncSetAttribute(hungarian_fused,
                         cudaFuncAttributeMaxDynamicSharedMemorySize, SMEM_SZ);
    hungarian_fused<<<BB, NT, SMEM_SZ>>>(logits, pboxes, tids, tboxes, imgsz, out);
}

// round 17
// speedup vs baseline: 1.1462x; 1.0300x over previous
#include <cuda_runtime.h>
#include <math.h>

#define BB 128
#define QQ 500
#define NCLS 80
#define TT 64
#define NT 1024
#define CSTR 516   // multiple of 4 for uint4 colscans; 4-way store conflict accepted
#define FULL 0xffffffffu
#define SMEM_SZ (TT * CSTR * 4)   // 132,096 B dynamic (Km only)
#define DEADK 0xFFFFFFFFu

__device__ __forceinline__ unsigned f2ord(float f) {
    unsigned u = __float_as_uint(f);
    return (u & 0x80000000u) ? ~u : (u | 0x80000000u);
}

// warp-cooperative exact (key, ravel) min over one key column.
// Rows 500..511 are padded DEADK so the 512-element vector scan needs no bounds check.
__device__ __forceinline__ void colscan(const unsigned* __restrict__ Km, int col,
                                        int lane, unsigned& mv, unsigned& mr) {
    const unsigned* p = Km + col * CSTR;
    // pass 1: tree-min over 16 values via 4 LDS.128 (MLP 4, conflict-free)
    uint4 a0 = *(const uint4*)(p + (lane << 2));
    uint4 a1 = *(const uint4*)(p + 128 + (lane << 2));
    uint4 a2 = *(const uint4*)(p + 256 + (lane << 2));
    uint4 a3 = *(const uint4*)(p + 384 + (lane << 2));
    unsigned b0 = umin(umin(a0.x, a0.y), umin(a0.z, a0.w));
    unsigned b1 = umin(umin(a1.x, a1.y), umin(a1.z, a1.w));
    unsigned b2 = umin(umin(a2.x, a2.y), umin(a2.z, a2.w));
    unsigned b3 = umin(umin(a3.x, a3.y), umin(a3.z, a3.w));
    unsigned best = umin(umin(b0, b1), umin(b2, b3));
    mv = __reduce_min_sync(FULL, best);

    // pass 2: smallest q with key == mv (assign order guarantees min q per lane)
    unsigned bq = 0xFFFFFFFFu;
    unsigned qb3 = 384 + (lane << 2);
    if (a3.w == mv) bq = qb3 + 3;
    if (a3.z == mv) bq = qb3 + 2;
    if (a3.y == mv) bq = qb3 + 1;
    if (a3.x == mv) bq = qb3;
    unsigned qb2 = 256 + (lane << 2);
    if (a2.w == mv) bq = qb2 + 3;
    if (a2.z == mv) bq = qb2 + 2;
    if (a2.y == mv) bq = qb2 + 1;
    if (a2.x == mv) bq = qb2;
    unsigned qb1 = 128 + (lane << 2);
    if (a1.w == mv) bq = qb1 + 3;
    if (a1.z == mv) bq = qb1 + 2;
    if (a1.y == mv) bq = qb1 + 1;
    if (a1.x == mv) bq = qb1;
    unsigned qb0 = (lane << 2);
    if (a0.w == mv) bq = qb0 + 3;
    if (a0.z == mv) bq = qb0 + 2;
    if (a0.y == mv) bq = qb0 + 1;
    if (a0.x == mv) bq = qb0;

    unsigned cr = (bq != 0xFFFFFFFFu) ? ((bq << 6) | (unsigned)col) : 0xFFFFFFFFu;
    mr = __reduce_min_sync(FULL, cr);
}

// one cost element; bit-identical ops to all passing rounds
__device__ __forceinline__ float cost_elem(float4 pb, float4 bn, float pa, float x,
                                           float4 tr, float4 tn, float ta) {
    float p = 1.0f / (1.0f + expf(-x));
    float omp = 1.0f - p;
    float pos = 0.25f * omp * omp * (-logf(p + 1e-8f));
    float neg = 0.75f * p * p * (-log1pf(-p + 1e-8f));
    float ccost = pos - neg;

    float l1 = fabsf(bn.x - tn.x) + fabsf(bn.y - tn.y)
             + fabsf(bn.z - tn.z) + fabsf(bn.w - tn.w);

    float iwd = fmaxf(fminf(pb.z, tr.z) - fmaxf(pb.x, tr.x), 0.0f);
    float ihd = fmaxf(fminf(pb.w, tr.w) - fmaxf(pb.y, tr.y), 0.0f);
    float inter = iwd * ihd;
    float uni = pa + ta - inter;
    float iou = inter / uni;
    float ewd = fmaxf(fmaxf(pb.z, tr.z) - fminf(pb.x, tr.x), 0.0f);
    float ehd = fmaxf(fmaxf(pb.w, tr.w) - fminf(pb.y, tr.y), 0.0f);
    float enc = ewd * ehd;
    float giou = iou - (enc - uni) / enc;

    return 5.0f * l1 + 2.0f * ccost - 2.0f * giou;
}

__global__ __launch_bounds__(NT, 1)
void hungarian_fused(const float* __restrict__ logits,   // [B,Q,C]
                     const float* __restrict__ pboxes,   // [B,Q,4]
                     const int*   __restrict__ tids,     // [B,T]
                     const float* __restrict__ tboxes,   // [B,T,4]
                     const float* __restrict__ imgsz,    // [B,4]
                     float*       __restrict__ out)
{
    extern __shared__ unsigned Km[];        // [64][516] f2ord keys
    __shared__ float4  s_tr[TT];
    __shared__ float4  s_tn[TT];
    __shared__ float   s_ta[TT];
    __shared__ int     s_cls[TT];
    __shared__ float4  s_pr[QQ];            // raw pred boxes
    __shared__ float4  s_bn[QQ];            // normalized pred boxes
    __shared__ float   s_pa[QQ];            // pred areas
    __shared__ unsigned s_val[TT], s_rav[TT];

    const int b = blockIdx.x, tid = threadIdx.x;
    const int lane = tid & 31, wrp = tid >> 5;

    const float inv0 = 1.0f / imgsz[b * 4 + 0];
    const float inv1 = 1.0f / imgsz[b * 4 + 1];
    const float inv2 = 1.0f / imgsz[b * 4 + 2];
    const float inv3 = 1.0f / imgsz[b * 4 + 3];

    if (tid < TT) {
        float4 tb = ((const float4*)tboxes)[b * TT + tid];
        s_tr[tid] = tb;
        s_tn[tid] = make_float4(tb.x * inv0, tb.y * inv1, tb.z * inv2, tb.w * inv3);
        s_ta[tid] = (tb.z - tb.x) * (tb.w - tb.y);
        s_cls[tid] = tids[b * TT + tid];
    }
    if (tid < QQ) {
        float4 pb = ((const float4*)pboxes)[b * QQ + tid];
        s_pr[tid] = pb;
        s_bn[tid] = make_float4(pb.x * inv0, pb.y * inv1, pb.z * inv2, pb.w * inv3);
        s_pa[tid] = (pb.z - pb.x) * (pb.w - pb.y);
    }
    // pad rows 500..511 of all 64 columns with DEADK (for vector colscans)
    if (tid < 768) {
        int col = tid / 12;
        int row = 500 + (tid - col * 12);
        Km[col * CSTR + row] = DEADK;
    }
    __syncthreads();

    // ---- Phase 1: 2 independent q-chains + software-pipelined logits prefetch ----
    const int t  = tid & 63;
    const int qg = tid >> 6;                 // 0..15
    const float4 tr = s_tr[t];
    const float4 tn = s_tn[t];
    const float  ta = s_ta[t];
    const int    cl = s_cls[t];

    const float* lg   = logits + (size_t)b * QQ * NCLS;
    float*       Cout = out    + (size_t)b * QQ * TT;

    float xA = __ldg(lg + qg * NCLS + cl);
    float xB = __ldg(lg + (qg + 16) * NCLS + cl);

    #pragma unroll 1
    for (int k2 = 0; k2 < 15; k2++) {
        int qa = qg + (k2 << 5);             // <= 495: always valid
        int qb = qa + 16;                    // <= 479 in-loop: always valid

        // prefetch next iteration's logits (hides LDG latency behind this body)
        int qa_n = qa + 32;
        int qb_n = qb + 32;
        float xA_n = __ldg(lg + qa_n * NCLS + cl);
        float xB_n = (qb_n < QQ) ? __ldg(lg + qb_n * NCLS + cl) : 0.0f;

        float cA = cost_elem(s_pr[qa], s_bn[qa], s_pa[qa], xA, tr, tn, ta);
        float cB = cost_elem(s_pr[qb], s_bn[qb], s_pa[qb], xB, tr, tn, ta);
        Km[t * CSTR + qa] = f2ord(cA);
        Cout[qa * TT + t] = cA;
        Km[t * CSTR + qb] = f2ord(cB);
        Cout[qb * TT + t] = cB;

        xA = xA_n; xB = xB_n;
    }
    {   // tail: qa = qg+480 always valid; qb = qg+496 valid only for qg < 4
        int qa = qg + 480;
        float cA = cost_elem(s_pr[qa], s_bn[qa], s_pa[qa], xA, tr, tn, ta);
        Km[t * CSTR + qa] = f2ord(cA);
        Cout[qa * TT + t] = cA;
        if (qg < 4) {
            int qb = qa + 16;
            float cB = cost_elem(s_pr[qb], s_bn[qb], s_pa[qb], xB, tr, tn, ta);
            Km[t * CSTR + qb] = f2ord(cB);
            Cout[qb * TT + t] = cB;
        }
    }
    __syncthreads();

    // ---- Phase 2: initial per-column (key, ravel) minima ----
    {
        unsigned mv, mr;
        colscan(Km, wrp, lane, mv, mr);
        if (lane == 0) { s_val[wrp] = mv; s_rav[wrp] = mr; }
        colscan(Km, wrp + 32, lane, mv, mr);
        if (lane == 0) { s_val[wrp + 32] = mv; s_rav[wrp + 32] = mr; }
    }
    __syncthreads();

    if (wrp != 0) return;   // greedy: warp 0 only

    // ---- Phase 3: greedy (R9-proven step body, key-array form) ----
    unsigned v0 = s_val[lane],      r0 = s_rav[lane];        // col = lane
    unsigned v1 = s_val[lane + 32], r1 = s_rav[lane + 32];   // col = lane+32

    float* rows_out = out + (size_t)BB * QQ * TT + (size_t)b * TT;
    float* cols_out = rows_out + (size_t)BB * TT;

    #pragma unroll 1
    for (int s = 0; s < TT; s++) {
        unsigned m = __reduce_min_sync(FULL, v0 < v1 ? v0 : v1);
        unsigned cand = 0xFFFFFFFFu;
        if (v0 == m) cand = r0;
        if (v1 == m && r1 < cand) cand = r1;
        unsigned r = __reduce_min_sync(FULL, cand);   // exact (value, ravel) tie-break

        int i = (int)(r >> 6);
        int j = (int)(r & 63u);
        if (lane == 0) { rows_out[s] = (float)i; cols_out[s] = (float)j; }
        if (s == TT - 1) break;

        // kill column j
        if (lane == (j & 31)) { if (j < 32) v0 = DEADK; else v1 = DEADK; }

        // rescan needs from register state before poisoning
        bool n0 = (v0 != DEADK) && ((r0 >> 6) == (unsigned)i);
        bool n1 = (v1 != DEADK) && ((r1 >> 6) == (unsigned)i);

        // poison row i in every column (max key) -> future scans maskless
        Km[lane * CSTR + i] = DEADK;
        Km[(lane + 32) * CSTR + i] = DEADK;

        unsigned bal0 = __ballot_sync(FULL, n0);
        unsigned bal1 = __ballot_sync(FULL, n1);
        if (bal0 | bal1) {
            __syncwarp();   // poisons visible before rescans
            while (bal0) {
                int c = __ffs(bal0) - 1; bal0 &= bal0 - 1;
                unsigned mv, mr;
                colscan(Km, c, lane, mv, mr);
                if (lane == c) { v0 = mv; r0 = mr; }
            }
            while (bal1) {
                int c = __ffs(bal1) - 1; bal1 &= bal1 - 1;
                unsigned mv, mr;
                colscan(Km, c + 32, lane, mv, mr);
                if (lane == c) { v1 = mv; r1 = mr; }
            }
        }
    }
}

extern "C" void kernel_launch(void* const* d_in, const int* in_sizes, int n_in,
                              void* d_out, int out_size) {
    const float* logits = (const float*)d_in[0];   // [128,500,80]
    const float* pboxes = (const float*)d_in[1];   // [128,500,4]
    const int*   tids   = (const int*)  d_in[2];   // [128,64]
    const float* tboxes = (const float*)d_in[3];   // [128,64,4]
    const float* imgsz  = (const float*)d_in[4];   // [128,4]
    float* out = (float*)d_out;

    cudaFuncSetAttribute(hungarian_fused,
                         cudaFuncAttributeMaxDynamicSharedMemorySize, SMEM_SZ);
    hungarian_fused<<<BB, NT, SMEM_SZ>>>(logits, pboxes, tids, tboxes, imgsz, out);
}